// round 15
// baseline (speedup 1.0000x reference)
#include <cuda_runtime.h>
#include <cuda_fp16.h>
#include <cstdint>
#include <cstddef>
#include <math.h>

#define G_    8192
#define IND_  512
#define KQD_  128
#define OUTD_ 512
#define NP_   768     // packed k|q|v columns
#define MTN_  640     // Mt columns = q(128) | v(512)
#define SPLITS_ 16

// ---------------- scratch (static __device__ = allowed) --------------------
__device__ __half h_x[(size_t)G_ * IND_];
__device__ __half h_w[(size_t)NP_ * IND_];        // packed [Wk;Wq;Wv] fp16
__device__ float  g_bias[NP_];                    // packed [bk;bq;bv]
__device__ __half h_kqv[(size_t)G_ * NP_];        // packed [k|q|v] fp16
__device__ float  g_part[(size_t)SPLITS_ * KQD_ * MTN_];  // split-K partials
__device__ __half h_b2[(size_t)MTN_ * 256];       // rows 0-511: W^T hi|lo ; 512-639: Gq hi|lo
__device__ __half h_k2[(size_t)G_ * 256];         // [g][k | k] (written by proj)
__device__ float  g_rinv[G_];

// ---------------- helpers ---------------------------------------------------
__device__ __forceinline__ uint32_t smem_u32(const void* p) {
    uint32_t a;
    asm("{ .reg .u64 t; cvta.to.shared.u64 t, %1; cvt.u32.u64 %0, t; }"
        : "=r"(a) : "l"(p));
    return a;
}
#define CP_ASYNC16(sm, gm) \
    asm volatile("cp.async.cg.shared.global [%0], [%1], 16;" :: "r"(sm), "l"(gm))
#define CP_COMMIT() asm volatile("cp.async.commit_group;" ::: "memory")
#define CP_WAIT(n)  asm volatile("cp.async.wait_group %0;" :: "n"(n) : "memory")

#define LDMX4(r0, r1, r2, r3, addr) \
    asm volatile("ldmatrix.sync.aligned.m8n8.x4.shared.b16 {%0,%1,%2,%3}, [%4];" \
                 : "=r"(r0), "=r"(r1), "=r"(r2), "=r"(r3) : "r"(addr))

#define LDMX4T(r0, r1, r2, r3, addr) \
    asm volatile("ldmatrix.sync.aligned.m8n8.x4.trans.shared.b16 {%0,%1,%2,%3}, [%4];" \
                 : "=r"(r0), "=r"(r1), "=r"(r2), "=r"(r3) : "r"(addr))

__device__ __forceinline__ void mma_f16(float* c, const uint32_t* a, const uint32_t* b) {
    asm volatile(
        "mma.sync.aligned.m16n8k16.row.col.f32.f16.f16.f32 "
        "{%0,%1,%2,%3}, {%4,%5,%6,%7}, {%8,%9}, {%0,%1,%2,%3};"
        : "+f"(c[0]), "+f"(c[1]), "+f"(c[2]), "+f"(c[3])
        : "r"(a[0]), "r"(a[1]), "r"(a[2]), "r"(a[3]), "r"(b[0]), "r"(b[1]));
}

// ===========================================================================
// FP16 GEMM-NT:  C[M,N] = A[M,K] @ B[N,K]^T  (half, row-major)
// Block 128x128, BK=32 halves, 4 warps, warp tile 64x64, 5-stage cp.async.
// MODE 0: Ch = h(acc + bias[col]); colBase==0 tile also writes k2=[k|k]
// MODE 4: no C store; ss[row] = sum_col acc*k[col] -> rinv_out[row]
// MODE 2: Cf[row*ldc+col] = rinv_in[row]*acc + float(kqv[row*NP_+512+col])
// ===========================================================================
template<int MODE>
__global__ void __launch_bounds__(128, 2)
mma_gemm(const __half* __restrict__ A, const __half* __restrict__ B,
         const float* __restrict__ bias, const float* __restrict__ rinv_in,
         const __half* __restrict__ kqv,
         __half* __restrict__ Ch, float* __restrict__ Cf,
         __half* __restrict__ k2out, float* __restrict__ rinv_out,
         int K, int lda, int ldb, int ldc)
{
    constexpr int STAGES = 5;
    constexpr int AS = 128 * 40;
    constexpr int BS = 128 * 40;

    extern __shared__ __half sm[];
    __shared__ float red[128][2];
    const uint32_t sAu = smem_u32(sm);
    const uint32_t sBu = smem_u32(sm + STAGES * AS);

    const int tid  = threadIdx.x;
    const int warp = tid >> 5;
    const int lane = tid & 31;
    const int gr   = lane >> 2;
    const int tc   = lane & 3;
    const int wm   = (warp & 1) * 64;
    const int wn   = (warp >> 1) * 64;
    const int rowBase = blockIdx.y * 128;
    const int colBase = blockIdx.x * 128;

    const int aRow  = wm + (lane & 15);
    const int aColH = (lane >> 4) << 3;
    const int bRow  = wn + ((lane >> 4) << 3) + (lane & 7);
    const int bColH = ((lane >> 3) & 1) << 3;

    float acc[4][8][4];
#pragma unroll
    for (int mi = 0; mi < 4; mi++)
#pragma unroll
        for (int ni = 0; ni < 8; ni++)
#pragma unroll
            for (int r = 0; r < 4; r++) acc[mi][ni][r] = 0.f;

    const int T = K / 32;

    auto load_stage = [&](int it, int buf) {
        const int k0 = it * 32;
#pragma unroll
        for (int l = 0; l < 4; l++) {
            int c = tid + l * 128;
            int r = c >> 2, ck = (c & 3) * 8;
            CP_ASYNC16(sAu + (uint32_t)(buf * AS + r * 40 + ck) * 2,
                       A + (size_t)(rowBase + r) * lda + k0 + ck);
        }
#pragma unroll
        for (int l = 0; l < 4; l++) {
            int c = tid + l * 128;
            int r = c >> 2, ck = (c & 3) * 8;
            CP_ASYNC16(sBu + (uint32_t)(buf * BS + r * 40 + ck) * 2,
                       B + (size_t)(colBase + r) * ldb + k0 + ck);
        }
        CP_COMMIT();
    };

#pragma unroll
    for (int s = 0; s < STAGES - 1; s++)
        if (s < T) load_stage(s, s);

    int buf = 0;
    for (int i = 0; i < T; i++) {
        const int rem = T - 1 - i;
        if (rem >= 3)      { CP_WAIT(3); }
        else if (rem == 2) { CP_WAIT(2); }
        else if (rem == 1) { CP_WAIT(1); }
        else               { CP_WAIT(0); }
        __syncthreads();
        if (i + STAGES - 1 < T) {
            int nb = buf + STAGES - 1; if (nb >= STAGES) nb -= STAGES;
            load_stage(i + STAGES - 1, nb);
        }

        const uint32_t cA = sAu + (uint32_t)(buf * AS) * 2;
        const uint32_t cB = sBu + (uint32_t)(buf * BS) * 2;
#pragma unroll
        for (int ks = 0; ks < 2; ks++) {
            const int kk = ks * 16;
            uint32_t a[4][4], b[8][2];
#pragma unroll
            for (int mi = 0; mi < 4; mi++) {
                uint32_t ad = cA + (uint32_t)((aRow + mi * 16) * 40 + kk + aColH) * 2;
                LDMX4(a[mi][0], a[mi][1], a[mi][2], a[mi][3], ad);
            }
#pragma unroll
            for (int p = 0; p < 4; p++) {
                uint32_t bd = cB + (uint32_t)((bRow + p * 16) * 40 + kk + bColH) * 2;
                LDMX4(b[2 * p][0], b[2 * p][1], b[2 * p + 1][0], b[2 * p + 1][1], bd);
            }
#pragma unroll
            for (int mi = 0; mi < 4; mi++)
#pragma unroll
                for (int ni = 0; ni < 8; ni++)
                    mma_f16(acc[mi][ni], a[mi], b[ni]);
        }
        buf++; if (buf >= STAGES) buf -= STAGES;
    }

    // ---------------- epilogues ----------------
#pragma unroll
    for (int mi = 0; mi < 4; mi++) {
#pragma unroll
        for (int h = 0; h < 2; h++) {
            const int lrow = wm + mi * 16 + h * 8 + gr;
            const int row  = rowBase + lrow;
            float part = 0.f;
            float rv = 0.f;
            if (MODE == 2) rv = rinv_in[row];
#pragma unroll
            for (int ni = 0; ni < 8; ni++) {
                const int col = colBase + wn + ni * 8 + tc * 2;
                float v0 = acc[mi][ni][h * 2 + 0];
                float v1 = acc[mi][ni][h * 2 + 1];
                if (MODE == 0) {
                    __half2 o = __floats2half2_rn(v0 + bias[col], v1 + bias[col + 1]);
                    *reinterpret_cast<__half2*>(Ch + (size_t)row * ldc + col) = o;
                    if (colBase == 0) {
                        *reinterpret_cast<__half2*>(k2out + (size_t)row * 256 + col) = o;
                        *reinterpret_cast<__half2*>(k2out + (size_t)row * 256 + 128 + col) = o;
                    }
                } else if (MODE == 4) {
                    float2 kk2 = __half22float2(
                        *reinterpret_cast<const __half2*>(kqv + (size_t)row * NP_ + col));
                    part += v0 * kk2.x + v1 * kk2.y;
                } else {
                    float2 vv = __half22float2(
                        *reinterpret_cast<const __half2*>(kqv + (size_t)row * NP_ + 2 * KQD_ + col));
                    float2 o;
                    o.x = rv * v0 + vv.x;
                    o.y = rv * v1 + vv.y;
                    *reinterpret_cast<float2*>(Cf + (size_t)row * ldc + col) = o;
                }
            }
            if (MODE == 4) {
                part += __shfl_xor_sync(0xffffffffu, part, 1);
                part += __shfl_xor_sync(0xffffffffu, part, 2);
                if (tc == 0) red[lrow][wn >> 6] = part;
            }
        }
    }
    if (MODE == 4) {
        __syncthreads();
        if (tid < 128) {
            float s = red[tid][0] + red[tid][1];
            rinv_out[rowBase + tid] = 1.0f / fmaxf(sqrtf(s), 1e-12f);
        }
    }
}

// ===========================================================================
// TN split-K GEMM: part[z][d][j] = sum_{g in slice z} kqv[g][128+d]*kqv[g][128+j]
// M=128 (d), N tile = 64 -> grid (10, 1, 16) = 160 CTAs.
// ===========================================================================
__global__ void __launch_bounds__(128, 2)
mt_tn(const __half* __restrict__ kqv, float* __restrict__ part)
{
    constexpr int STAGES = 4;
    constexpr int TSA = 32 * 136;
    constexpr int TSB = 32 * 72;

    extern __shared__ __half sm[];
    const uint32_t sAu = smem_u32(sm);
    const uint32_t sBu = smem_u32(sm + STAGES * TSA);

    const int tid  = threadIdx.x;
    const int warp = tid >> 5;
    const int lane = tid & 31;
    const int gr   = lane >> 2;
    const int tc   = lane & 3;
    const int wm   = (warp & 1) * 64;
    const int wn   = (warp >> 1) * 32;
    const int n0   = blockIdx.x * 64;
    const int zb   = blockIdx.z * (G_ / SPLITS_);

    const int aKr = ((lane >> 4) << 3) + (lane & 7);
    const int aMc = ((lane >> 3) & 1) << 3;
    const int bKr = (((lane >> 3) & 1) << 3) + (lane & 7);
    const int bNc = (lane >> 4) << 3;

    float acc[4][4][4];
#pragma unroll
    for (int mi = 0; mi < 4; mi++)
#pragma unroll
        for (int ni = 0; ni < 4; ni++)
#pragma unroll
            for (int r = 0; r < 4; r++) acc[mi][ni][r] = 0.f;

    const int T = (G_ / SPLITS_) / 32;

    auto load_stage = [&](int it, int buf) {
        const int g0 = zb + it * 32;
#pragma unroll
        for (int l = 0; l < 4; l++) {
            int c = tid + l * 128;
            int gro = c >> 4, gc = (c & 15) * 8;
            CP_ASYNC16(sAu + (uint32_t)(buf * TSA + gro * 136 + gc) * 2,
                       kqv + (size_t)(g0 + gro) * NP_ + KQD_ + gc);
        }
#pragma unroll
        for (int l = 0; l < 2; l++) {
            int c = tid + l * 128;
            int gro = c >> 3, gc = (c & 7) * 8;
            CP_ASYNC16(sBu + (uint32_t)(buf * TSB + gro * 72 + gc) * 2,
                       kqv + (size_t)(g0 + gro) * NP_ + KQD_ + n0 + gc);
        }
        CP_COMMIT();
    };

#pragma unroll
    for (int s = 0; s < STAGES - 1; s++)
        load_stage(s, s);

    int buf = 0;
    for (int i = 0; i < T; i++) {
        const int rem = T - 1 - i;
        if (rem >= 2)      { CP_WAIT(2); }
        else if (rem == 1) { CP_WAIT(1); }
        else               { CP_WAIT(0); }
        __syncthreads();
        if (i + STAGES - 1 < T) {
            int nb = buf + STAGES - 1; if (nb >= STAGES) nb -= STAGES;
            load_stage(i + STAGES - 1, nb);
        }

        const uint32_t cA = sAu + (uint32_t)(buf * TSA) * 2;
        const uint32_t cB = sBu + (uint32_t)(buf * TSB) * 2;
#pragma unroll
        for (int ks = 0; ks < 2; ks++) {
            const int kk = ks * 16;
            uint32_t a[4][4], b[4][2];
#pragma unroll
            for (int mi = 0; mi < 4; mi++) {
                uint32_t ad = cA + (uint32_t)((kk + aKr) * 136 + wm + mi * 16 + aMc) * 2;
                LDMX4T(a[mi][0], a[mi][1], a[mi][2], a[mi][3], ad);
            }
#pragma unroll
            for (int p = 0; p < 2; p++) {
                uint32_t bd = cB + (uint32_t)((kk + bKr) * 72 + wn + p * 16 + bNc) * 2;
                LDMX4T(b[2 * p][0], b[2 * p][1], b[2 * p + 1][0], b[2 * p + 1][1], bd);
            }
#pragma unroll
            for (int mi = 0; mi < 4; mi++)
#pragma unroll
                for (int ni = 0; ni < 4; ni++)
                    mma_f16(acc[mi][ni], a[mi], b[ni]);
        }
        buf++; if (buf >= STAGES) buf -= STAGES;
    }

    float* dst = part + (size_t)blockIdx.z * KQD_ * MTN_;
#pragma unroll
    for (int mi = 0; mi < 4; mi++)
#pragma unroll
        for (int h = 0; h < 2; h++) {
            const int d = wm + mi * 16 + h * 8 + gr;
#pragma unroll
            for (int ni = 0; ni < 4; ni++) {
                const int col = n0 + wn + ni * 8 + tc * 2;
                float2 o;
                o.x = acc[mi][ni][h * 2 + 0];
                o.y = acc[mi][ni][h * 2 + 1];
                *reinterpret_cast<float2*>(dst + (size_t)d * MTN_ + col) = o;
            }
        }
}

// ---------------------------------------------------------------------------
__global__ void prep(const float* __restrict__ x,
                     const float* __restrict__ wk, const float* __restrict__ wq,
                     const float* __restrict__ wv,
                     const float* __restrict__ bk, const float* __restrict__ bq,
                     const float* __restrict__ bv,
                     __half* __restrict__ hx, __half* __restrict__ hw,
                     float* __restrict__ gb)
{
    const int NX = G_ * IND_ / 2;
    const int NW = NP_ * IND_ / 2;
    int i = blockIdx.x * 256 + threadIdx.x;
    if (i < NX) {
        float2 v = reinterpret_cast<const float2*>(x)[i];
        reinterpret_cast<__half2*>(hx)[i] = __floats2half2_rn(v.x, v.y);
    } else if (i < NX + NW) {
        int j = i - NX;
        int row = j / (IND_ / 2), c2 = j % (IND_ / 2);
        const float* src; int sr;
        if (row < KQD_)          { src = wk; sr = row; }
        else if (row < 2 * KQD_) { src = wq; sr = row - KQD_; }
        else                     { src = wv; sr = row - 2 * KQD_; }
        float2 v = reinterpret_cast<const float2*>(src + (size_t)sr * IND_)[c2];
        reinterpret_cast<__half2*>(hw + (size_t)row * IND_)[c2] = __floats2half2_rn(v.x, v.y);
    } else if (i < NX + NW + NP_) {
        int j = i - NX - NW;
        gb[j] = (j < KQD_) ? bk[j] : (j < 2 * KQD_) ? bq[j - KQD_] : bv[j - 2 * KQD_];
    }
}

// ===========================================================================
// mt_reduce: block owns 8 j-columns x all 128 d. Coalesced reads (j fast),
// smem transpose, coalesced row-contiguous b2 writes. grid 80 x 256.
// Summation order over z identical to before (z = 0..15 sequential).
// ===========================================================================
__global__ void __launch_bounds__(256)
mt_reduce(const float* __restrict__ part, __half* __restrict__ b2)
{
    __shared__ float tile[8][132];

    const int tid = threadIdx.x;
    const int j0  = blockIdx.x * 8;
    const int jj  = tid & 7;          // 0..7
    const int dg  = tid >> 3;         // 0..31

    // accumulate: thread handles d = dg + 32*c for c = 0..3
#pragma unroll
    for (int c = 0; c < 4; c++) {
        const int d = dg + 32 * c;
        float s = 0.f;
#pragma unroll
        for (int z = 0; z < SPLITS_; z++)
            s += part[(size_t)z * KQD_ * MTN_ + (size_t)d * MTN_ + j0 + jj];
        tile[jj][d] = s;
    }
    __syncthreads();

    // write phase: warp w handles b2 row for j = j0 + w; lanes cover d.
    const int jr   = tid >> 5;        // 0..7
    const int lane = tid & 31;
    const int j    = j0 + jr;
    const int r    = (j < KQD_) ? (512 + j) : (j - KQD_);
    const int d0   = lane * 4;

    float4 s4 = *reinterpret_cast<const float4*>(&tile[jr][d0]);
    float sv[4] = {s4.x, s4.y, s4.z, s4.w};
    __half hi4[4], lo4[4];
#pragma unroll
    for (int e = 0; e < 4; e++) {
        hi4[e] = __float2half_rn(sv[e]);
        lo4[e] = __float2half_rn(sv[e] - __half2float(hi4[e]));
    }
    *reinterpret_cast<uint2*>(b2 + (size_t)r * 256 + d0) =
        *reinterpret_cast<uint2*>(hi4);
    *reinterpret_cast<uint2*>(b2 + (size_t)r * 256 + 128 + d0) =
        *reinterpret_cast<uint2*>(lo4);
}

// ---------------------------------------------------------------------------
extern "C" void kernel_launch(void* const* d_in, const int* in_sizes, int n_in,
                              void* d_out, int out_size)
{
    const float* x  = (const float*)d_in[0];
    const float* Wk = (const float*)d_in[1];
    const float* bk = (const float*)d_in[2];
    const float* Wq = (const float*)d_in[3];
    const float* bq = (const float*)d_in[4];
    const float* Wv = (const float*)d_in[5];
    const float* bv = (const float*)d_in[6];
    float* out = (float*)d_out;
    (void)in_sizes; (void)n_in; (void)out_size;

    __half *px, *pw, *pkqv, *pb2, *pk2;
    float *pb, *ppart, *pr;
    cudaGetSymbolAddress((void**)&px,    h_x);
    cudaGetSymbolAddress((void**)&pw,    h_w);
    cudaGetSymbolAddress((void**)&pb,    g_bias);
    cudaGetSymbolAddress((void**)&pkqv,  h_kqv);
    cudaGetSymbolAddress((void**)&ppart, g_part);
    cudaGetSymbolAddress((void**)&pb2,   h_b2);
    cudaGetSymbolAddress((void**)&pk2,   h_k2);
    cudaGetSymbolAddress((void**)&pr,    g_rinv);

    const int smemB = 5 * (128 * 40 + 128 * 40) * 2;   // 102400 B
    cudaFuncSetAttribute(mma_gemm<0>, cudaFuncAttributeMaxDynamicSharedMemorySize, smemB);
    cudaFuncSetAttribute(mma_gemm<4>, cudaFuncAttributeMaxDynamicSharedMemorySize, smemB);
    cudaFuncSetAttribute(mma_gemm<2>, cudaFuncAttributeMaxDynamicSharedMemorySize, smemB);
    const int smemT = 4 * (32 * 136 + 32 * 72) * 2;    // 53248 B
    cudaFuncSetAttribute(mt_tn, cudaFuncAttributeMaxDynamicSharedMemorySize, smemT);

    // prep (x->fp16, W pack, bias pack)
    const int NPREP = G_ * IND_ / 2 + NP_ * IND_ / 2 + NP_;
    prep<<<(NPREP + 255) / 256, 256>>>(x, Wk, Wq, Wv, bk, bq, bv, px, pw, pb);

    // fused QKV projection (emits kqv and k2=[k|k])
    mma_gemm<0><<<dim3(NP_ / 128, G_ / 128), 128, smemB>>>(
        px, pw, pb, nullptr, nullptr, pkqv, nullptr, pk2, nullptr,
        IND_, IND_, IND_, NP_);

    // Mt = q^T @ [q|v] (TN split-K) -> reduce into B2 (smem-staged writes)
    mt_tn<<<dim3(MTN_ / 64, 1, SPLITS_), 128, smemT>>>(pkqv, ppart);
    mt_reduce<<<MTN_ / 8, 256>>>(ppart, pb2);

    // rinv: y = k @ Gq (N=128), ss = y.k computed in-register -> rinv
    mma_gemm<4><<<dim3(1, G_ / 128), 128, smemB>>>(
        pk2, pb2 + (size_t)512 * 256, nullptr, nullptr, pkqv,
        nullptr, nullptr, nullptr, pr, 256, 256, 256, KQD_);

    // out = rinv[row] * (k @ W) + v   (N=512, writes out directly)
    mma_gemm<2><<<dim3(OUTD_ / 128, G_ / 128), 128, smemB>>>(
        pk2, pb2, nullptr, pr, pkqv, nullptr, out, nullptr, nullptr,
        256, 256, 256, OUTD_);
}